// round 16
// baseline (speedup 1.0000x reference)
#include <cuda_runtime.h>
#include <cuda_fp16.h>
#include <math.h>
#include <stdint.h>

// Problem constants
constexpr int cB  = 16;
constexpr int cH  = 8;
constexpr int cNL = 256;
constexpr int cNP = 2048;
constexpr int cD  = 64;          // HID
constexpr int cNT = cNL + cNP;   // 2304

// ---------------- scratch (device globals; no runtime allocation) ----------------
__device__ __half g_L1h [cB * cH * cNL * cD];        // [bh][l][d]  fp16 (relu)
__device__ float  g_L2t [cB * cH * cD * cNL];        // [bh][d][l]  fp32 (atv A operand)
__device__ __half g_P1h [cB * cH * cNP * cD];        // [bh][p][d]  fp16
__device__ __half g_P2th[cB * cH * cD * cNP];        // [bh][d][p]  fp16
__device__ __half g_att[(size_t)cB * cH * cNL * cNP];// e at historical max scale, fp16
__device__ float  g_mthen[cB * cH * 32 * cNL];       // [bh][pt][l] running max at tile pt
__device__ float  g_sinv[cB * cH * cNL];             // 1 / row-sum of e
__device__ float  g_l3h[cB * cNL * cH * cD];         // [B, Nl, 512]
__device__ float  g_p3h[cB * cNP * cH * cD];         // [B, Np, 512]
// transposed + tf32-rounded weights
__device__ float  g_wT [4][512 * 64];                // proj: [(h*64+n)][k]
__device__ float  g_f1T[2][64 * 512];                // fc11/fc21: [n][k]
__device__ float  g_f2T[2][64 * 128];                // fc12/fc22: [n][k]

// ---------------- helpers ----------------
__device__ __forceinline__ float tf32f(float x) {
    uint32_t u;
    asm("cvt.rna.tf32.f32 %0, %1;" : "=r"(u) : "f"(x));
    return __uint_as_float(u);
}

__device__ __forceinline__ uint32_t h2u(__half2 h) {
    union { __half2 h; uint32_t u; } cvt;
    cvt.h = h;
    return cvt.u;
}

__device__ __forceinline__ void mma_tf32(float d[4], const uint32_t a[4], const uint32_t b[2]) {
    asm volatile(
        "mma.sync.aligned.m16n8k8.row.col.f32.tf32.tf32.f32 "
        "{%0,%1,%2,%3}, {%4,%5,%6,%7}, {%8,%9}, {%0,%1,%2,%3};\n"
        : "+f"(d[0]), "+f"(d[1]), "+f"(d[2]), "+f"(d[3])
        : "r"(a[0]), "r"(a[1]), "r"(a[2]), "r"(a[3]), "r"(b[0]), "r"(b[1]));
}

__device__ __forceinline__ void mma_f16(float d[4], const uint32_t a[4], const uint32_t b[2]) {
    asm volatile(
        "mma.sync.aligned.m16n8k16.row.col.f32.f16.f16.f32 "
        "{%0,%1,%2,%3}, {%4,%5,%6,%7}, {%8,%9}, {%0,%1,%2,%3};\n"
        : "+f"(d[0]), "+f"(d[1]), "+f"(d[2]), "+f"(d[3])
        : "r"(a[0]), "r"(a[1]), "r"(a[2]), "r"(a[3]), "r"(b[0]), "r"(b[1]));
}

__device__ __forceinline__ void cpa16(void* smem, const void* g) {
    uint32_t s = (uint32_t)__cvta_generic_to_shared(smem);
    asm volatile("cp.async.cg.shared.global [%0], [%1], 16;" :: "r"(s), "l"(g) : "memory");
}
#define CP_COMMIT() asm volatile("cp.async.commit_group;" ::: "memory")
#define CP_WAIT(n)  asm volatile("cp.async.wait_group %0;" :: "n"(n) : "memory")

#define AS(r_, c_) As[(r_) * 68 + (c_)]
#define BS(r_, c_) Bs[(r_) * 68 + (c_)]
#define CS(r_, c_) As[(r_) * 68 + (c_)]   // stage aliases As region

__device__ __forceinline__ void load_afr(const float* As_, int m0, int grp, int qid,
                                         int kk, uint32_t a[4]) {
    const int k0 = kk * 8;
    a[0] = __float_as_uint(As_[(m0 + grp) * 68 + k0 + qid]);
    a[1] = __float_as_uint(As_[(m0 + grp + 8) * 68 + k0 + qid]);
    a[2] = __float_as_uint(As_[(m0 + grp) * 68 + k0 + qid + 4]);
    a[3] = __float_as_uint(As_[(m0 + grp + 8) * 68 + k0 + qid + 4]);
}

__device__ __forceinline__ void load_bfr(const float* Bs_, int n, int kk, int qid,
                                         uint32_t b[2]) {
    const int k0 = kk * 8;
    b[0] = __float_as_uint(Bs_[n * 68 + k0 + qid]);
    b[1] = __float_as_uint(Bs_[n * 68 + k0 + qid + 4]);
}

// fp16 fragment loads from half tiles with row stride 72 halves
__device__ __forceinline__ void load_afr_h(const __half* T, int m0, int grp, int qid,
                                           int kk, uint32_t a[4]) {
    const int k0 = kk * 16 + 2 * qid;
    a[0] = *(const uint32_t*)&T[(m0 + grp) * 72 + k0];
    a[1] = *(const uint32_t*)&T[(m0 + grp + 8) * 72 + k0];
    a[2] = *(const uint32_t*)&T[(m0 + grp) * 72 + k0 + 8];
    a[3] = *(const uint32_t*)&T[(m0 + grp + 8) * 72 + k0 + 8];
}

__device__ __forceinline__ void load_bfr_h(const __half* T, int n, int kk, int qid,
                                           uint32_t b[2]) {
    const int k0 = kk * 16 + 2 * qid;
    b[0] = *(const uint32_t*)&T[n * 72 + k0];
    b[1] = *(const uint32_t*)&T[n * 72 + k0 + 8];
}

// =====================================================================
// prep: transpose + tf32-round all weights once.
// =====================================================================
__global__ __launch_bounds__(256) void prep_weights(
    const float* __restrict__ wl1, const float* __restrict__ wl2,
    const float* __restrict__ wp1, const float* __restrict__ wp2,
    const float* __restrict__ f11, const float* __restrict__ f21,
    const float* __restrict__ f12, const float* __restrict__ f22) {
    int i = blockIdx.x * 256 + threadIdx.x;
    if (i < 4 * 32768) {
        int w = i >> 15, r = i & 32767;          // r = hn*64 + k
        int hn = r >> 6, k = r & 63;
        const float* src = (w == 0) ? wl1 : (w == 1) ? wl2 : (w == 2) ? wp1 : wp2;
        g_wT[w][r] = tf32f(src[(size_t)k * 512 + hn]);
    } else if (i < 6 * 32768) {
        int j = i - 4 * 32768;
        int w = j >> 15, r = j & 32767;          // r = n*512 + k
        int n = r >> 9, k = r & 511;
        const float* src = w ? f21 : f11;
        g_f1T[w][r] = tf32f(src[(size_t)k * 64 + n]);
    } else if (i < 6 * 32768 + 2 * 8192) {
        int j = i - 6 * 32768;
        int w = j >> 13, r = j & 8191;           // r = n*128 + k
        int n = r >> 7, k = r & 127;
        const float* src = w ? f22 : f12;
        g_f2T[w][r] = tf32f(src[(size_t)k * 64 + n]);
    }
}

// =====================================================================
// proj2 (merged lig+prot): wsel 0 -> fp16 [bh][n][d] (L1h/P1h);
// wsel 1, which 0 -> fp32 [bh][d][n] (L2t); wsel 1, which 1 -> fp16 (P2th).
// =====================================================================
__global__ __launch_bounds__(256) void proj2(const float* __restrict__ lig,
                                             const float* __restrict__ prot,
                                             const float* __restrict__ bl1,
                                             const float* __restrict__ bl2,
                                             const float* __restrict__ bp1,
                                             const float* __restrict__ bp2) {
    __shared__ float As[64 * 68];
    __shared__ float Bs[64 * 68];
    const int which = (blockIdx.x >= 64) ? 1 : 0;
    const int bx = which ? (blockIdx.x - 64) : blockIdx.x;
    const float* x = which ? prot : lig;
    const float* bA = which ? bp1 : bl1;
    const float* bB = which ? bp2 : bl2;
    const int N = which ? cNP : cNL;
    const int row0 = bx * 64;
    const int tid = threadIdx.x;

    for (int i = tid; i < 1024; i += 256) {
        int r = i >> 4, c4 = (i & 15) * 4;
        float4 v = *(const float4*)&x[(size_t)(row0 + r) * 64 + c4];
        v.x = tf32f(v.x); v.y = tf32f(v.y); v.z = tf32f(v.z); v.w = tf32f(v.w);
        *(float4*)&AS(r, c4) = v;
    }
    __syncthreads();

    const int wid = tid >> 5, lane = tid & 31, grp = lane >> 2, qid = lane & 3;
    const int mtw = wid & 3, nw = wid >> 2;
    const int m0 = mtw * 16, n0 = nw * 32;
    uint32_t afr[8][4];
#pragma unroll
    for (int kk = 0; kk < 8; kk++) load_afr(As, m0, grp, qid, kk, afr[kk]);

    const int b = row0 / N, nbase = row0 % N;
    const int r0l = m0 + grp, r1l = r0l + 8;

    for (int it = 0; it < 16; it++) {
        const int wsel = it >> 3, h = it & 7;
        const float* wT = g_wT[which * 2 + wsel];
        const float* bias = wsel ? bB : bA;

        __syncthreads();   // prev iter's CS reads done
        for (int i = tid; i < 1024; i += 256) {
            int n = i >> 4, k4 = (i & 15) * 4;
            cpa16(&BS(n, k4), &wT[(size_t)(h * 64 + n) * 64 + k4]);
        }
        CP_COMMIT();
        CP_WAIT(0);
        __syncthreads();

        float acc[4][4] = {};
#pragma unroll
        for (int kk = 0; kk < 8; kk++) {
#pragma unroll
            for (int t = 0; t < 4; t++) {
                uint32_t bf[2];
                load_bfr(Bs, n0 + t * 8 + grp, kk, qid, bf);
                mma_tf32(acc[t], afr[kk], bf);
            }
        }

        if (wsel == 0) {
            __half* outp = which ? g_P1h : g_L1h;
#pragma unroll
            for (int t = 0; t < 4; t++) {
                int c = n0 + t * 8 + 2 * qid;
                float bv0 = bias[h * 64 + c], bv1 = bias[h * 64 + c + 1];
                CS(r0l, c)     = fmaxf(acc[t][0] + bv0, 0.f);
                CS(r0l, c + 1) = fmaxf(acc[t][1] + bv1, 0.f);
                CS(r1l, c)     = fmaxf(acc[t][2] + bv0, 0.f);
                CS(r1l, c + 1) = fmaxf(acc[t][3] + bv1, 0.f);
            }
            __syncthreads();
            for (int i = tid; i < 1024; i += 256) {
                int r = i >> 4, c4 = (i & 15) * 4;
                float4 v = *(float4*)&CS(r, c4);
                uint2 o;
                o.x = h2u(__floats2half2_rn(v.x, v.y));
                o.y = h2u(__floats2half2_rn(v.z, v.w));
                *(uint2*)&outp[(((size_t)b * cH + h) * N + nbase + r) * 64 + c4] = o;
            }
        } else {
#pragma unroll
            for (int t = 0; t < 4; t++) {
                int c = n0 + t * 8 + 2 * qid;
                float bv0 = bias[h * 64 + c], bv1 = bias[h * 64 + c + 1];
                CS(c, r0l)     = tf32f(fmaxf(acc[t][0] + bv0, 0.f));
                CS(c + 1, r0l) = tf32f(fmaxf(acc[t][1] + bv1, 0.f));
                CS(c, r1l)     = tf32f(fmaxf(acc[t][2] + bv0, 0.f));
                CS(c + 1, r1l) = tf32f(fmaxf(acc[t][3] + bv1, 0.f));
            }
            __syncthreads();
            if (which == 0) {
                for (int i = tid; i < 1024; i += 256) {
                    int d = i >> 4, r4 = (i & 15) * 4;
                    *(float4*)&g_L2t[(((size_t)b * cH + h) * 64 + d) * N + nbase + r4] =
                        *(float4*)&CS(d, r4);
                }
            } else {
                for (int i = tid; i < 1024; i += 256) {
                    int d = i >> 4, r4 = (i & 15) * 4;
                    float4 v = *(float4*)&CS(d, r4);
                    uint2 o;
                    o.x = h2u(__floats2half2_rn(v.x, v.y));
                    o.y = h2u(__floats2half2_rn(v.z, v.w));
                    *(uint2*)&g_P2th[(((size_t)b * cH + h) * 64 + d) * N + nbase + r4] = o;
                }
            }
        }
    }
}

// =====================================================================
// energy_av (fp16 MMA m16n8k16): online softmax, warp-autonomous rows,
// cp.async half tiles (8KB each), split-group P1/P2 overlap.
// =====================================================================
__global__ void __launch_bounds__(128, 4) energy_av(const float* __restrict__ dist) {
    __shared__ __half P1h[64 * 72];      // L1 tile (init) / P1 tile / e-stage overlay
    __shared__ __half P2h[64 * 72];      // P2 tiles
    const int bh = blockIdx.y, b = bh >> 3, h = bh & 7;
    const int l0 = blockIdx.x * 64;
    const int tid = threadIdx.x, wid = tid >> 5, lane = tid & 31;
    const int grp = lane >> 2, qid = lane & 3;

    // L1 tile -> P1h (cp.async), hoist A fragments (fp16)
    const __half* Ag = g_L1h + ((size_t)bh * cNL + l0) * 64;
    for (int i = tid; i < 512; i += 128) {
        int r = i >> 3, k8 = (i & 7) * 8;
        cpa16(&P1h[r * 72 + k8], &Ag[(size_t)r * 64 + k8]);
    }
    CP_COMMIT();
    CP_WAIT(0);
    __syncthreads();
    uint32_t afr[4][4];
#pragma unroll
    for (int kk = 0; kk < 4; kk++) load_afr_h(P1h, wid * 16, grp, qid, kk, afr[kk]);

    const __half* Bbase = g_P1h + (size_t)bh * cNP * 64;
    const __half* P2b   = g_P2th + (size_t)bh * 64 * cNP;
    __half* eh = g_att + ((size_t)bh * cNL + l0) * cNP;
    const int lr0 = wid * 16 + grp, lr1 = lr0 + 8;      // local row in 64-block
    const size_t drow0 = ((size_t)(b * cNL) + l0 + lr0) * cNP;
    const size_t drow1 = ((size_t)(b * cNL) + l0 + lr1) * cNP;
    __half* estw = &P1h[wid * 16 * 72];  // e-stage: warp-private 16x72-half chunk
    const float hf = (float)h;

    float mold0 = 0.f, mold1 = 0.f, s0 = 0.f, s1 = 0.f;  // masked logits = 0
    float accv[8][4] = {};   // av accumulator over d (8 n-tiles)

    for (int pt = 0; pt < 32; pt++) {
        const int p0 = pt * 64;
        __syncthreads();                     // B1: prev tile fully consumed
        for (int i = tid; i < 512; i += 128) {
            int p = i >> 3, k8 = (i & 7) * 8;
            cpa16(&P1h[p * 72 + k8], &Bbase[(size_t)(p0 + p) * 64 + k8]);
        }
        CP_COMMIT();                         // group A: P1 tile
        for (int i = tid; i < 512; i += 128) {
            int dd = i >> 3, p8 = (i & 7) * 8;
            cpa16(&P2h[dd * 72 + p8], &P2b[(size_t)dd * cNP + p0 + p8]);
        }
        CP_COMMIT();                         // group B: P2 tile
        CP_WAIT(1);                          // P1 landed; P2 still in flight
        __syncthreads();                     // B2: P1 visible block-wide

        // energy MMA (fp16): m=16 x n=64, k=64 in 4 chunks of 16
        float acc[8][4] = {};
#pragma unroll
        for (int kk = 0; kk < 4; kk++)
#pragma unroll
            for (int t = 0; t < 8; t++) {
                uint32_t bf[2];
                load_bfr_h(P1h, t * 8 + grp, kk, qid, bf);
                mma_f16(acc[t], afr[kk], bf);
            }

        // mask + logits (in place) + tile max
        float tx0 = -1e30f, tx1 = -1e30f;
#pragma unroll
        for (int t = 0; t < 8; t++) {
            const int c = p0 + t * 8 + 2 * qid;
            const float2 dv0 = *(const float2*)&dist[drow0 + c];
            const float2 dv1 = *(const float2*)&dist[drow1 + c];
            const float dd[4] = {dv0.x, dv0.y, dv1.x, dv1.y};
#pragma unroll
            for (int j = 0; j < 4; j++) {
                const float d = dd[j];
                const bool msk = (h < 7) ? (d > hf && d <= hf + 3.0f) : (d > 7.0f);
                const float inter = msk ? __fdividef(1.0f, d) : 0.0f;
                acc[t][j] = acc[t][j] * 0.125f * inter;
            }
            tx0 = fmaxf(tx0, fmaxf(acc[t][0], acc[t][1]));
            tx1 = fmaxf(tx1, fmaxf(acc[t][2], acc[t][3]));
        }
        tx0 = fmaxf(tx0, __shfl_xor_sync(0xffffffffu, tx0, 1));
        tx0 = fmaxf(tx0, __shfl_xor_sync(0xffffffffu, tx0, 2));
        tx1 = fmaxf(tx1, __shfl_xor_sync(0xffffffffu, tx1, 1));
        tx1 = fmaxf(tx1, __shfl_xor_sync(0xffffffffu, tx1, 2));
        const float mn0 = fmaxf(mold0, tx0), mn1 = fmaxf(mold1, tx1);
        const float f0 = __expf(mold0 - mn0), f1 = __expf(mold1 - mn1);
        mold0 = mn0; mold1 = mn1;

        CP_WAIT(0);                          // P2 landed (overlapped with MMA)
        __syncthreads();                     // B3: P1h reads done + P2 visible

        float ps0 = 0.f, ps1 = 0.f;
#pragma unroll
        for (int t = 0; t < 8; t++) {
            float e0 = __expf(acc[t][0] - mn0), e1 = __expf(acc[t][1] - mn0);
            float e2 = __expf(acc[t][2] - mn1), e3 = __expf(acc[t][3] - mn1);
            const __half2 h01 = __floats2half2_rn(e0, e1);
            const __half2 h23 = __floats2half2_rn(e2, e3);
            const float2 q01 = __half22float2(h01), q23 = __half22float2(h23);
            ps0 += q01.x + q01.y; ps1 += q23.x + q23.y;
            const int cc = t * 8 + 2 * qid;
            *(__half2*)&estw[grp * 72 + cc]       = h01;
            *(__half2*)&estw[(grp + 8) * 72 + cc] = h23;
            *(__half2*)&eh[(size_t)lr0 * cNP + p0 + cc] = h01;
            *(__half2*)&eh[(size_t)lr1 * cNP + p0 + cc] = h23;
            accv[t][0] *= f0; accv[t][1] *= f0; accv[t][2] *= f1; accv[t][3] *= f1;
        }
        s0 = s0 * f0 + ps0; s1 = s1 * f1 + ps1;
        if (qid == 0) {
            g_mthen[((size_t)bh * 32 + pt) * cNL + l0 + lr0] = mn0;
            g_mthen[((size_t)bh * 32 + pt) * cNL + l0 + lr1] = mn1;
        }
        __syncwarp();                        // est visible within warp

        // av MMA (fp16): A = e (est), B = P2 tile
#pragma unroll
        for (int kk = 0; kk < 4; kk++) {
            uint32_t a[4];
            load_afr_h(estw, 0, grp, qid, kk, a);
#pragma unroll
            for (int t = 0; t < 8; t++) {
                uint32_t bf[2];
                load_bfr_h(P2h, t * 8 + grp, kk, qid, bf);
                mma_f16(accv[t], a, bf);
            }
        }
    }

    // finalize: quad-reduce sums, write sinv + l3h
    s0 += __shfl_xor_sync(0xffffffffu, s0, 1);
    s0 += __shfl_xor_sync(0xffffffffu, s0, 2);
    s1 += __shfl_xor_sync(0xffffffffu, s1, 1);
    s1 += __shfl_xor_sync(0xffffffffu, s1, 2);
    const float inv0 = 1.0f / s0, inv1 = 1.0f / s1;
    if (qid == 0) {
        g_sinv[bh * cNL + l0 + lr0] = inv0;
        g_sinv[bh * cNL + l0 + lr1] = inv1;
    }
    const size_t orow0 = ((size_t)(b * cNL) + l0 + lr0) * 512 + h * 64;
    const size_t orow1 = ((size_t)(b * cNL) + l0 + lr1) * 512 + h * 64;
#pragma unroll
    for (int t = 0; t < 8; t++) {
        const int cc = t * 8 + 2 * qid;
        *(float2*)&g_l3h[orow0 + cc] =
            make_float2(accv[t][0] * inv0, accv[t][1] * inv0);
        *(float2*)&g_l3h[orow1 + cc] =
            make_float2(accv[t][2] * inv1, accv[t][3] * inv1);
    }
}

// =====================================================================
// atv v3 (FP16 MMA, transpose-free): D[d][p] = sum_l A[d][l] * e[l][p]
// where A[half][d][l] = fp16(L2t[d][l] * sinv[l] * cf[pt0+half][l]).
// e tile stored raw fp16, k-pair-packed: Aep[k/2][n] = (e[k][n], e[k+1][n]).
// m = d (64), n = p (128 per block), k = l (tiles of 32, 2 mma-k16 chunks).
// =====================================================================
__global__ __launch_bounds__(256) void atv_mma() {
    __shared__ __half2 Aep[16 * 136];    // e pairs [k/2][p=128], stride 136 (8704B)
    __shared__ __half  A2h[2][64 * 40];  // per-half scaled L2t [d][l=32] (10240B)
    __shared__ float cfa[2][256];
    __shared__ float svs[256];
#define ATS(p_, d_) ((float*)Aep)[(p_) * 68 + (d_)]  // stage overlays Aep+A2h (17408B<18944B)
    const int bh = blockIdx.y, b = bh >> 3, h = bh & 7;
    const int p0 = blockIdx.x * 128;
    const int tid = threadIdx.x, wid = tid >> 5, lane = tid & 31, grp = lane >> 2, qid = lane & 3;
    const int mtw = wid & 3, nw = wid >> 2;   // 4 d-tiles x 2 p-halves
    const int m0 = mtw * 16, n0 = nw * 64;
    const __half* eb = g_att + (size_t)bh * cNL * cNP;
    const float* L2b = g_L2t + (size_t)bh * 64 * cNL;
    const float* sv = g_sinv + (size_t)bh * cNL;
    const int pt0 = p0 >> 6;

    for (int i = tid; i < 512; i += 256) {
        int v = i >> 8, j = i & 255;
        float mf = g_mthen[((size_t)bh * 32 + 31) * cNL + j];
        float mt = g_mthen[((size_t)bh * 32 + pt0 + v) * cNL + j];
        cfa[v][j] = __expf(mt - mf);
    }
    for (int i = tid; i < 256; i += 256) svs[i] = sv[i];

    // prefetch tile lt=0: e rows 2kp, 2kp+1 (8 p each) + L2 row chunk
    const int kp = tid >> 4, c8 = (tid & 15) * 8;       // e-fill coords
    const int dL = tid >> 2, k8 = (tid & 3) * 8;        // L2-fill coords (8 l per thread)
    uint4 eRa, eRb;
    float4 l2Ra, l2Rb;
    eRa = *(const uint4*)&eb[(size_t)(2 * kp) * cNP + p0 + c8];
    eRb = *(const uint4*)&eb[(size_t)(2 * kp + 1) * cNP + p0 + c8];
    l2Ra = *(const float4*)&L2b[(size_t)dL * cNL + k8];
    l2Rb = *(const float4*)&L2b[(size_t)dL * cNL + k8 + 4];

    float acc[8][4] = {};
    for (int lt = 0; lt < 8; lt++) {
        const int lb = lt * 32;
        __syncthreads();   // prev MMA done; cfa/svs ready on first iter
        // e pairs: interleave rows 2kp/2kp+1 -> half2 (k,k+1)
        {
            __half2 ha[4], hb[4];
            *(uint4*)ha = eRa;
            *(uint4*)hb = eRb;
            __half2 o[8];
#pragma unroll
            for (int j = 0; j < 4; j++) {
                o[2 * j]     = __lows2half2(ha[j], hb[j]);
                o[2 * j + 1] = __highs2half2(ha[j], hb[j]);
            }
            *(uint4*)&Aep[kp * 136 + c8]     = *(uint4*)&o[0];
            *(uint4*)&Aep[kp * 136 + c8 + 4] = *(uint4*)&o[4];
        }
        // A: L2t * sv * cf[half], fp16, both halves
        {
            const float* cf0 = cfa[0], *cf1 = cfa[1];
            float vs[8] = { l2Ra.x, l2Ra.y, l2Ra.z, l2Ra.w, l2Rb.x, l2Rb.y, l2Rb.z, l2Rb.w };
            __half2 o0[4], o1[4];
#pragma unroll
            for (int j = 0; j < 4; j++) {
                const int l = lb + k8 + 2 * j;
                float b0 = vs[2 * j] * svs[l], b1 = vs[2 * j + 1] * svs[l + 1];
                o0[j] = __floats2half2_rn(b0 * cf0[l], b1 * cf0[l + 1]);
                o1[j] = __floats2half2_rn(b0 * cf1[l], b1 * cf1[l + 1]);
            }
            *(uint4*)&A2h[0][dL * 40 + k8] = *(uint4*)&o0[0];
            *(uint4*)&A2h[1][dL * 40 + k8] = *(uint4*)&o1[0];
        }
        // prefetch lt+1 (LDGs overlap the MMA below)
        if (lt < 7) {
            const int lb2 = lb + 32;
            eRa = *(const uint4*)&eb[(size_t)(lb2 + 2 * kp) * cNP + p0 + c8];
            eRb = *(const uint4*)&eb[(size_t)(lb2 + 2 * kp + 1) * cNP + p0 + c8];
            l2Ra = *(const float4*)&L2b[(size_t)dL * cNL + lb2 + k8];
            l2Rb = *(const float4*)&L2b[(size_t)dL * cNL + lb2 + k8 + 4];
        }
        __syncthreads();
        const __half* Aw = A2h[nw];
#pragma unroll
        for (int kk = 0; kk < 2; kk++) {
            const int k0 = kk * 16;
            uint32_t a[4] = {
                *(const uint32_t*)&Aw[(m0 + grp) * 40 + k0 + 2 * qid],
                *(const uint32_t*)&Aw[(m0 + grp + 8) * 40 + k0 + 2 * qid],
                *(const uint32_t*)&Aw[(m0 + grp) * 40 + k0 + 2 * qid + 8],
                *(const uint32_t*)&Aw[(m0 + grp + 8) * 40 + k0 + 2 * qid + 8] };
#pragma unroll
            for (int t = 0; t < 8; t++) {
                const int n = n0 + t * 8 + grp;
                uint32_t bf[2] = { h2u(Aep[(kk * 8 + qid) * 136 + n]),
                                   h2u(Aep[(kk * 8 + qid + 4) * 136 + n]) };
                mma_f16(acc[t], a, bf);
            }
        }
    }

    // Epilogue: D[d][p] -> stage [p][d] -> coalesced p3h writes, two p-halves
#pragma unroll
    for (int half = 0; half < 2; half++) {
        __syncthreads();
        if (nw == half) {
            const int d0 = m0 + grp, d1 = d0 + 8;
#pragma unroll
            for (int t = 0; t < 8; t++) {
                const int pl = t * 8 + 2 * qid;
                ATS(pl, d0)     = tf32f(acc[t][0]);
                ATS(pl + 1, d0) = tf32f(acc[t][1]);
                ATS(pl, d1)     = tf32f(acc[t][2]);
                ATS(pl + 1, d1) = tf32f(acc[t][3]);
            }
        }
        __syncthreads();
        const int pg = p0 + half * 64;
        for (int i = tid; i < 1024; i += 256) {
            int pl = i >> 4, c4 = (i & 15) * 4;
            *(float4*)&g_p3h[((size_t)(b * cNP) + pg + pl) * 512 + h * 64 + c4] =
                *(float4*)&ATS(pl, c4);
        }
    }
#undef ATS
}

// =====================================================================
// fc_fused (merged lig+prot) with 2-stage cp.async PIPELINE for fc1 (K=32 tiles).
// =====================================================================
__global__ __launch_bounds__(256) void fc_fused(const float* __restrict__ lig,
                                                const float* __restrict__ prot,
                                                const float* __restrict__ b1l,
                                                const float* __restrict__ b2l,
                                                const float* __restrict__ b1p,
                                                const float* __restrict__ b2p,
                                                float* __restrict__ out) {
    __shared__ float SM[9216];
#define A1(buf_, r_, k_) SM[(buf_) * 2304 + (r_) * 36 + (k_)]
#define B1(buf_, n_, k_) SM[4608 + (buf_) * 2304 + (n_) * 36 + (k_)]
#define CSF(r_, c_) SM[(r_) * 68 + (c_)]
    float* B2s = SM + 4608;   // fc2 weight tile, stride 68
    const int which = (blockIdx.x >= 64) ? 1 : 0;
    const int bx = which ? (blockIdx.x - 64) : blockIdx.x;
    const float* X = which ? g_p3h : g_l3h;
    const float* W1 = g_f1T[which];
    const float* W2 = g_f2T[which];
    const float* orig = which ? prot : lig;
    const float* b1 = which ? b1p : b1l;
    const float* b2 = which ? b2p : b2l;
    const int N = which ? cNP : cNL;
    const int row_off = which ? cNL : 0;
    const int row0 = bx * 64;
    const int tid = threadIdx.x, wid = tid >> 5, lane = tid & 31, grp = lane >> 2, qid = lane & 3;
    const int mtw = wid & 3, nw = wid >> 2, m0 = mtw * 16, n0 = nw * 32;
    const int r0l = m0 + grp, r1l = r0l + 8;

#define FILL_KT(kt_, buf_)                                                        \
    do {                                                                          \
        const int kb_ = (kt_) * 32;                                               \
        for (int i = tid; i < 512; i += 256) {                                    \
            int r_ = i >> 3, k4_ = (i & 7) * 4;                                   \
            cpa16(&A1(buf_, r_, k4_), &X[(size_t)(row0 + r_) * 512 + kb_ + k4_]); \
        }                                                                         \
        for (int i = tid; i < 512; i += 256) {                                    \
            int n_ = i >> 3, k4_ = (i & 7) * 4;                                   \
            cpa16(&B1(buf_, n_, k4_), &W1[(size_t)n_ * 512 + kb_ + k4_]);         \
        }                                                                         \
        CP_COMMIT();                                                              \
    } while (0)

    FILL_KT(0, 0);
    FILL_KT(1, 1);

    float acc[4][4] = {};
    for (int kt = 0; kt < 16; kt++) {
        if (kt < 15) { CP_WAIT(1); } else { CP_WAIT(0); }
        __syncthreads();
        const int buf = kt & 1;
#pragma unroll
        for (int kk = 0; kk < 4; kk++) {
            const int k0 = kk * 8;
            uint32_t a[4] = { __float_as_uint(A1(buf, m0 + grp, k0 + qid)),
                              __float_as_uint(A1(buf, m0 + grp + 8, k0 + qid)),
                              __float_as_uint(A1(buf, m0 + grp, k0 + qid + 4)),
                              __float_as_uint(A1(buf, m0 + grp + 8, k0 + qid + 4)) };
#pragma unroll
            for (int t = 0; t < 4; t++) {
                const int n = n0 + t * 8 + grp;
                uint32_t bf[2] = { __float_as_uint(B1(buf, n, k0 + qid)),
                                   __float_as_uint(B1(buf, n, k0 + qid + 4)) };
                mma_tf32(acc[t], a, bf);
            }
        }
        __syncthreads();
        if (kt + 2 < 16) FILL_KT(kt + 2, kt & 1);
    }
#undef FILL_KT

#pragma unroll
    for (int t = 0; t < 4; t++) {
        const int c = n0 + t * 8 + 2 * qid;
        const float bv0 = b1[c], bv1 = b1[c + 1];
        CSF(r0l, c)     = tf32f(acc[t][0] + bv0);
        CSF(r0l, c + 1) = tf32f(acc[t][1] + bv1);
        CSF(r1l, c)     = tf32f(acc[t][2] + bv0);
        CSF(r1l, c + 1) = tf32f(acc[t][3] + bv1);
    }
    for (int i = tid; i < 1024; i += 256) {
        int n = i >> 4, k4 = (i & 15) * 4;
        cpa16(&B2s[n * 68 + k4], &W2[(size_t)n * 128 + k4]);
    }
    CP_COMMIT();
    CP_WAIT(0);
    __syncthreads();

    float acc2[4][4] = {};
#pragma unroll
    for (int kk = 0; kk < 8; kk++) {
        uint32_t a[4];
        load_afr(SM, m0, grp, qid, kk, a);
#pragma unroll
        for (int t = 0; t < 4; t++) {
            uint32_t bf[2];
            load_bfr(B2s, n0 + t * 8 + grp, kk, qid, bf);
            mma_tf32(acc2[t], a, bf);
        }
    }
    __syncthreads();
    for (int i = tid; i < 1024; i += 256) {
        int r = i >> 4, c4 = (i & 15) * 4;
        float4 v = *(const float4*)&orig[(size_t)(row0 + r) * 64 + c4];
        v.x = tf32f(v.x); v.y = tf32f(v.y); v.z = tf32f(v.z); v.w = tf32f(v.w);
        *(float4*)&CSF(r, c4) = v;
    }
    for (int i = tid; i < 1024; i += 256) {
        int n = i >> 4, k4 = (i & 15) * 4;
        cpa16(&B2s[n * 68 + k4], &W2[(size_t)n * 128 + 64 + k4]);
    }
    CP_COMMIT();
    CP_WAIT(0);
    __syncthreads();
#pragma unroll
    for (int kk = 0; kk < 8; kk++) {
        uint32_t a[4];
        load_afr(SM, m0, grp, qid, kk, a);
#pragma unroll
        for (int t = 0; t < 4; t++) {
            uint32_t bf[2];
            load_bfr(B2s, n0 + t * 8 + grp, kk, qid, bf);
            mma_tf32(acc2[t], a, bf);
        }
    }
    __syncthreads();
#pragma unroll
    for (int t = 0; t < 4; t++) {
        const int c = n0 + t * 8 + 2 * qid;
        const float bv0 = b2[c], bv1 = b2[c + 1];
        CSF(r0l, c)     = fmaxf(acc2[t][0] + bv0, 0.f);
        CSF(r0l, c + 1) = fmaxf(acc2[t][1] + bv1, 0.f);
        CSF(r1l, c)     = fmaxf(acc2[t][2] + bv0, 0.f);
        CSF(r1l, c + 1) = fmaxf(acc2[t][3] + bv1, 0.f);
    }
    __syncthreads();
    const int b = row0 / N, nbase = row0 % N;
    for (int i = tid; i < 1024; i += 256) {
        int r = i >> 4, c4 = (i & 15) * 4;
        *(float4*)&out[((size_t)b * cNT + row_off + nbase + r) * 64 + c4] =
            *(float4*)&CSF(r, c4);
    }
#undef A1
#undef B1
#undef CSF
}

// =====================================================================
extern "C" void kernel_launch(void* const* d_in, const int* in_sizes, int n_in,
                              void* d_out, int out_size) {
    (void)in_sizes; (void)n_in; (void)out_size;
    const float* ligand = (const float*)d_in[0];
    const float* prot   = (const float*)d_in[1];
    const float* dist   = (const float*)d_in[2];
    const float* b_l1 = (const float*)d_in[4];
    const float* b_l2 = (const float*)d_in[6];
    const float* b_p1 = (const float*)d_in[8];
    const float* b_p2 = (const float*)d_in[10];
    const float* fc11_b = (const float*)d_in[12];
    const float* fc12_b = (const float*)d_in[14];
    const float* fc21_b = (const float*)d_in[16];
    const float* fc22_b = (const float*)d_in[18];
    float* out = (float*)d_out;

    prep_weights<<<832, 256>>>((const float*)d_in[3], (const float*)d_in[5],
                               (const float*)d_in[7], (const float*)d_in[9],
                               (const float*)d_in[11], (const float*)d_in[15],
                               (const float*)d_in[13], (const float*)d_in[17]);
    proj2<<<576, 256>>>(ligand, prot, b_l1, b_l2, b_p1, b_p2);
    energy_av<<<dim3(cNL / 64, cB * cH), 128>>>(dist);
    atv_mma<<<dim3(cNP / 128, cB * cH), 256>>>();
    fc_fused<<<576, 256>>>(ligand, prot, fc11_b, fc12_b, fc21_b, fc22_b, out);
}

// round 17
// speedup vs baseline: 1.5138x; 1.5138x over previous
#include <cuda_runtime.h>
#include <cuda_fp16.h>
#include <math.h>
#include <stdint.h>

// Problem constants
constexpr int cB  = 16;
constexpr int cH  = 8;
constexpr int cNL = 256;
constexpr int cNP = 2048;
constexpr int cD  = 64;          // HID
constexpr int cNT = cNL + cNP;   // 2304

// ---------------- scratch (device globals; no runtime allocation) ----------------
__device__ __half g_L1h [cB * cH * cNL * cD];        // [bh][l][d]  fp16 (relu)
__device__ float  g_L2t [cB * cH * cD * cNL];        // [bh][d][l]  fp32 (atv A operand)
__device__ __half g_P1h [cB * cH * cNP * cD];        // [bh][p][d]  fp16
__device__ __half g_P2th[cB * cH * cD * cNP];        // [bh][d][p]  fp16
__device__ __half g_att[(size_t)cB * cH * cNL * cNP];// e at historical max scale, fp16
__device__ float  g_mthen[cB * cH * 32 * cNL];       // [bh][pt][l] running max at tile pt
__device__ float  g_sinv[cB * cH * cNL];             // 1 / row-sum of e
__device__ float  g_l3h[cB * cNL * cH * cD];         // [B, Nl, 512]
__device__ float  g_p3h[cB * cNP * cH * cD];         // [B, Np, 512]
// transposed + tf32-rounded weights
__device__ float  g_wT [4][512 * 64];                // proj: [(h*64+n)][k]
__device__ float  g_f1T[2][64 * 512];                // fc11/fc21: [n][k]
__device__ float  g_f2T[2][64 * 128];                // fc12/fc22: [n][k]

// ---------------- helpers ----------------
__device__ __forceinline__ float tf32f(float x) {
    uint32_t u;
    asm("cvt.rna.tf32.f32 %0, %1;" : "=r"(u) : "f"(x));
    return __uint_as_float(u);
}

__device__ __forceinline__ uint32_t h2u(__half2 h) {
    union { __half2 h; uint32_t u; } cvt;
    cvt.h = h;
    return cvt.u;
}

__device__ __forceinline__ void mma_tf32(float d[4], const uint32_t a[4], const uint32_t b[2]) {
    asm volatile(
        "mma.sync.aligned.m16n8k8.row.col.f32.tf32.tf32.f32 "
        "{%0,%1,%2,%3}, {%4,%5,%6,%7}, {%8,%9}, {%0,%1,%2,%3};\n"
        : "+f"(d[0]), "+f"(d[1]), "+f"(d[2]), "+f"(d[3])
        : "r"(a[0]), "r"(a[1]), "r"(a[2]), "r"(a[3]), "r"(b[0]), "r"(b[1]));
}

__device__ __forceinline__ void mma_f16(float d[4], const uint32_t a[4], const uint32_t b[2]) {
    asm volatile(
        "mma.sync.aligned.m16n8k16.row.col.f32.f16.f16.f32 "
        "{%0,%1,%2,%3}, {%4,%5,%6,%7}, {%8,%9}, {%0,%1,%2,%3};\n"
        : "+f"(d[0]), "+f"(d[1]), "+f"(d[2]), "+f"(d[3])
        : "r"(a[0]), "r"(a[1]), "r"(a[2]), "r"(a[3]), "r"(b[0]), "r"(b[1]));
}

__device__ __forceinline__ void cpa16(void* smem, const void* g) {
    uint32_t s = (uint32_t)__cvta_generic_to_shared(smem);
    asm volatile("cp.async.cg.shared.global [%0], [%1], 16;" :: "r"(s), "l"(g) : "memory");
}
#define CP_COMMIT() asm volatile("cp.async.commit_group;" ::: "memory")
#define CP_WAIT(n)  asm volatile("cp.async.wait_group %0;" :: "n"(n) : "memory")

#define AS(r_, c_) As[(r_) * 68 + (c_)]
#define BS(r_, c_) Bs[(r_) * 68 + (c_)]
#define CS(r_, c_) As[(r_) * 68 + (c_)]   // stage aliases As region

__device__ __forceinline__ void load_afr(const float* As_, int m0, int grp, int qid,
                                         int kk, uint32_t a[4]) {
    const int k0 = kk * 8;
    a[0] = __float_as_uint(As_[(m0 + grp) * 68 + k0 + qid]);
    a[1] = __float_as_uint(As_[(m0 + grp + 8) * 68 + k0 + qid]);
    a[2] = __float_as_uint(As_[(m0 + grp) * 68 + k0 + qid + 4]);
    a[3] = __float_as_uint(As_[(m0 + grp + 8) * 68 + k0 + qid + 4]);
}

__device__ __forceinline__ void load_bfr(const float* Bs_, int n, int kk, int qid,
                                         uint32_t b[2]) {
    const int k0 = kk * 8;
    b[0] = __float_as_uint(Bs_[n * 68 + k0 + qid]);
    b[1] = __float_as_uint(Bs_[n * 68 + k0 + qid + 4]);
}

// fp16 fragment loads from half tiles with row stride 72 halves
__device__ __forceinline__ void load_afr_h(const __half* T, int m0, int grp, int qid,
                                           int kk, uint32_t a[4]) {
    const int k0 = kk * 16 + 2 * qid;
    a[0] = *(const uint32_t*)&T[(m0 + grp) * 72 + k0];
    a[1] = *(const uint32_t*)&T[(m0 + grp + 8) * 72 + k0];
    a[2] = *(const uint32_t*)&T[(m0 + grp) * 72 + k0 + 8];
    a[3] = *(const uint32_t*)&T[(m0 + grp + 8) * 72 + k0 + 8];
}

__device__ __forceinline__ void load_bfr_h(const __half* T, int n, int kk, int qid,
                                           uint32_t b[2]) {
    const int k0 = kk * 16 + 2 * qid;
    b[0] = *(const uint32_t*)&T[n * 72 + k0];
    b[1] = *(const uint32_t*)&T[n * 72 + k0 + 8];
}

// =====================================================================
// prep: transpose + tf32-round all weights once.
// =====================================================================
__global__ __launch_bounds__(256) void prep_weights(
    const float* __restrict__ wl1, const float* __restrict__ wl2,
    const float* __restrict__ wp1, const float* __restrict__ wp2,
    const float* __restrict__ f11, const float* __restrict__ f21,
    const float* __restrict__ f12, const float* __restrict__ f22) {
    int i = blockIdx.x * 256 + threadIdx.x;
    if (i < 4 * 32768) {
        int w = i >> 15, r = i & 32767;          // r = hn*64 + k
        int hn = r >> 6, k = r & 63;
        const float* src = (w == 0) ? wl1 : (w == 1) ? wl2 : (w == 2) ? wp1 : wp2;
        g_wT[w][r] = tf32f(src[(size_t)k * 512 + hn]);
    } else if (i < 6 * 32768) {
        int j = i - 4 * 32768;
        int w = j >> 15, r = j & 32767;          // r = n*512 + k
        int n = r >> 9, k = r & 511;
        const float* src = w ? f21 : f11;
        g_f1T[w][r] = tf32f(src[(size_t)k * 64 + n]);
    } else if (i < 6 * 32768 + 2 * 8192) {
        int j = i - 6 * 32768;
        int w = j >> 13, r = j & 8191;           // r = n*128 + k
        int n = r >> 7, k = r & 127;
        const float* src = w ? f22 : f12;
        g_f2T[w][r] = tf32f(src[(size_t)k * 64 + n]);
    }
}

// =====================================================================
// proj2 (merged lig+prot) with PIPELINED weight prefetch: tile it+1's
// cp.async issues right after tile it's MMA, overlapping the epilogue.
// wsel 0 -> fp16 [bh][n][d] (L1h/P1h); wsel 1, which 0 -> fp32 [bh][d][n]
// (L2t); wsel 1, which 1 -> fp16 (P2th).
// =====================================================================
__global__ __launch_bounds__(256) void proj2(const float* __restrict__ lig,
                                             const float* __restrict__ prot,
                                             const float* __restrict__ bl1,
                                             const float* __restrict__ bl2,
                                             const float* __restrict__ bp1,
                                             const float* __restrict__ bp2) {
    __shared__ float As[64 * 68];
    __shared__ float Bs[64 * 68];
    const int which = (blockIdx.x >= 64) ? 1 : 0;
    const int bx = which ? (blockIdx.x - 64) : blockIdx.x;
    const float* x = which ? prot : lig;
    const float* bA = which ? bp1 : bl1;
    const float* bB = which ? bp2 : bl2;
    const int N = which ? cNP : cNL;
    const int row0 = bx * 64;
    const int tid = threadIdx.x;

    for (int i = tid; i < 1024; i += 256) {
        int r = i >> 4, c4 = (i & 15) * 4;
        float4 v = *(const float4*)&x[(size_t)(row0 + r) * 64 + c4];
        v.x = tf32f(v.x); v.y = tf32f(v.y); v.z = tf32f(v.z); v.w = tf32f(v.w);
        *(float4*)&AS(r, c4) = v;
    }
    // prefetch weight tile for it=0 (h=0, wsel=0); overlaps x-tile visibility
    {
        const float* wT0 = g_wT[which * 2];
        for (int i = tid; i < 1024; i += 256) {
            int n = i >> 4, k4 = (i & 15) * 4;
            cpa16(&BS(n, k4), &wT0[(size_t)n * 64 + k4]);
        }
        CP_COMMIT();
    }
    __syncthreads();

    const int wid = tid >> 5, lane = tid & 31, grp = lane >> 2, qid = lane & 3;
    const int mtw = wid & 3, nw = wid >> 2;
    const int m0 = mtw * 16, n0 = nw * 32;
    uint32_t afr[8][4];
#pragma unroll
    for (int kk = 0; kk < 8; kk++) load_afr(As, m0, grp, qid, kk, afr[kk]);

    const int b = row0 / N, nbase = row0 % N;
    const int r0l = m0 + grp, r1l = r0l + 8;

    for (int it = 0; it < 16; it++) {
        const int wsel = it >> 3, h = it & 7;
        const float* bias = wsel ? bB : bA;

        CP_WAIT(0);
        __syncthreads();   // Bs visible; prev iter's CS reads done

        float acc[4][4] = {};
#pragma unroll
        for (int kk = 0; kk < 8; kk++) {
#pragma unroll
            for (int t = 0; t < 4; t++) {
                uint32_t bf[2];
                load_bfr(Bs, n0 + t * 8 + grp, kk, qid, bf);
                mma_tf32(acc[t], afr[kk], bf);
            }
        }
        __syncthreads();   // all Bs reads done

        // prefetch next weight tile; copy overlaps epilogue below
        if (it < 15) {
            const int it2 = it + 1;
            const float* wT2 = g_wT[which * 2 + (it2 >> 3)];
            const int h2 = it2 & 7;
            for (int i = tid; i < 1024; i += 256) {
                int n = i >> 4, k4 = (i & 15) * 4;
                cpa16(&BS(n, k4), &wT2[(size_t)(h2 * 64 + n) * 64 + k4]);
            }
            CP_COMMIT();
        }

        if (wsel == 0) {
            __half* outp = which ? g_P1h : g_L1h;
#pragma unroll
            for (int t = 0; t < 4; t++) {
                int c = n0 + t * 8 + 2 * qid;
                float bv0 = bias[h * 64 + c], bv1 = bias[h * 64 + c + 1];
                CS(r0l, c)     = fmaxf(acc[t][0] + bv0, 0.f);
                CS(r0l, c + 1) = fmaxf(acc[t][1] + bv1, 0.f);
                CS(r1l, c)     = fmaxf(acc[t][2] + bv0, 0.f);
                CS(r1l, c + 1) = fmaxf(acc[t][3] + bv1, 0.f);
            }
            __syncthreads();
            for (int i = tid; i < 1024; i += 256) {
                int r = i >> 4, c4 = (i & 15) * 4;
                float4 v = *(float4*)&CS(r, c4);
                uint2 o;
                o.x = h2u(__floats2half2_rn(v.x, v.y));
                o.y = h2u(__floats2half2_rn(v.z, v.w));
                *(uint2*)&outp[(((size_t)b * cH + h) * N + nbase + r) * 64 + c4] = o;
            }
        } else {
#pragma unroll
            for (int t = 0; t < 4; t++) {
                int c = n0 + t * 8 + 2 * qid;
                float bv0 = bias[h * 64 + c], bv1 = bias[h * 64 + c + 1];
                CS(c, r0l)     = tf32f(fmaxf(acc[t][0] + bv0, 0.f));
                CS(c + 1, r0l) = tf32f(fmaxf(acc[t][1] + bv1, 0.f));
                CS(c, r1l)     = tf32f(fmaxf(acc[t][2] + bv0, 0.f));
                CS(c + 1, r1l) = tf32f(fmaxf(acc[t][3] + bv1, 0.f));
            }
            __syncthreads();
            if (which == 0) {
                for (int i = tid; i < 1024; i += 256) {
                    int d = i >> 4, r4 = (i & 15) * 4;
                    *(float4*)&g_L2t[(((size_t)b * cH + h) * 64 + d) * N + nbase + r4] =
                        *(float4*)&CS(d, r4);
                }
            } else {
                for (int i = tid; i < 1024; i += 256) {
                    int d = i >> 4, r4 = (i & 15) * 4;
                    float4 v = *(float4*)&CS(d, r4);
                    uint2 o;
                    o.x = h2u(__floats2half2_rn(v.x, v.y));
                    o.y = h2u(__floats2half2_rn(v.z, v.w));
                    *(uint2*)&g_P2th[(((size_t)b * cH + h) * 64 + d) * N + nbase + r4] = o;
                }
            }
        }
    }
}

// =====================================================================
// energy_av (fp16 MMA m16n8k16): online softmax, warp-autonomous rows,
// cp.async half tiles (8KB each), split-group P1/P2 overlap.
// =====================================================================
__global__ void __launch_bounds__(128, 4) energy_av(const float* __restrict__ dist) {
    __shared__ __half P1h[64 * 72];      // L1 tile (init) / P1 tile / e-stage overlay
    __shared__ __half P2h[64 * 72];      // P2 tiles
    const int bh = blockIdx.y, b = bh >> 3, h = bh & 7;
    const int l0 = blockIdx.x * 64;
    const int tid = threadIdx.x, wid = tid >> 5, lane = tid & 31;
    const int grp = lane >> 2, qid = lane & 3;

    // L1 tile -> P1h (cp.async), hoist A fragments (fp16)
    const __half* Ag = g_L1h + ((size_t)bh * cNL + l0) * 64;
    for (int i = tid; i < 512; i += 128) {
        int r = i >> 3, k8 = (i & 7) * 8;
        cpa16(&P1h[r * 72 + k8], &Ag[(size_t)r * 64 + k8]);
    }
    CP_COMMIT();
    CP_WAIT(0);
    __syncthreads();
    uint32_t afr[4][4];
#pragma unroll
    for (int kk = 0; kk < 4; kk++) load_afr_h(P1h, wid * 16, grp, qid, kk, afr[kk]);

    const __half* Bbase = g_P1h + (size_t)bh * cNP * 64;
    const __half* P2b   = g_P2th + (size_t)bh * 64 * cNP;
    __half* eh = g_att + ((size_t)bh * cNL + l0) * cNP;
    const int lr0 = wid * 16 + grp, lr1 = lr0 + 8;      // local row in 64-block
    const size_t drow0 = ((size_t)(b * cNL) + l0 + lr0) * cNP;
    const size_t drow1 = ((size_t)(b * cNL) + l0 + lr1) * cNP;
    __half* estw = &P1h[wid * 16 * 72];  // e-stage: warp-private 16x72-half chunk
    const float hf = (float)h;

    float mold0 = 0.f, mold1 = 0.f, s0 = 0.f, s1 = 0.f;  // masked logits = 0
    float accv[8][4] = {};   // av accumulator over d (8 n-tiles)

    for (int pt = 0; pt < 32; pt++) {
        const int p0 = pt * 64;
        __syncthreads();                     // B1: prev tile fully consumed
        for (int i = tid; i < 512; i += 128) {
            int p = i >> 3, k8 = (i & 7) * 8;
            cpa16(&P1h[p * 72 + k8], &Bbase[(size_t)(p0 + p) * 64 + k8]);
        }
        CP_COMMIT();                         // group A: P1 tile
        for (int i = tid; i < 512; i += 128) {
            int dd = i >> 3, p8 = (i & 7) * 8;
            cpa16(&P2h[dd * 72 + p8], &P2b[(size_t)dd * cNP + p0 + p8]);
        }
        CP_COMMIT();                         // group B: P2 tile
        CP_WAIT(1);                          // P1 landed; P2 still in flight
        __syncthreads();                     // B2: P1 visible block-wide

        // energy MMA (fp16): m=16 x n=64, k=64 in 4 chunks of 16
        float acc[8][4] = {};
#pragma unroll
        for (int kk = 0; kk < 4; kk++)
#pragma unroll
            for (int t = 0; t < 8; t++) {
                uint32_t bf[2];
                load_bfr_h(P1h, t * 8 + grp, kk, qid, bf);
                mma_f16(acc[t], afr[kk], bf);
            }

        // mask + logits (in place) + tile max
        float tx0 = -1e30f, tx1 = -1e30f;
#pragma unroll
        for (int t = 0; t < 8; t++) {
            const int c = p0 + t * 8 + 2 * qid;
            const float2 dv0 = *(const float2*)&dist[drow0 + c];
            const float2 dv1 = *(const float2*)&dist[drow1 + c];
            const float dd[4] = {dv0.x, dv0.y, dv1.x, dv1.y};
#pragma unroll
            for (int j = 0; j < 4; j++) {
                const float d = dd[j];
                const bool msk = (h < 7) ? (d > hf && d <= hf + 3.0f) : (d > 7.0f);
                const float inter = msk ? __fdividef(1.0f, d) : 0.0f;
                acc[t][j] = acc[t][j] * 0.125f * inter;
            }
            tx0 = fmaxf(tx0, fmaxf(acc[t][0], acc[t][1]));
            tx1 = fmaxf(tx1, fmaxf(acc[t][2], acc[t][3]));
        }
        tx0 = fmaxf(tx0, __shfl_xor_sync(0xffffffffu, tx0, 1));
        tx0 = fmaxf(tx0, __shfl_xor_sync(0xffffffffu, tx0, 2));
        tx1 = fmaxf(tx1, __shfl_xor_sync(0xffffffffu, tx1, 1));
        tx1 = fmaxf(tx1, __shfl_xor_sync(0xffffffffu, tx1, 2));
        const float mn0 = fmaxf(mold0, tx0), mn1 = fmaxf(mold1, tx1);
        const float f0 = __expf(mold0 - mn0), f1 = __expf(mold1 - mn1);
        mold0 = mn0; mold1 = mn1;

        CP_WAIT(0);                          // P2 landed (overlapped with MMA)
        __syncthreads();                     // B3: P1h reads done + P2 visible

        float ps0 = 0.f, ps1 = 0.f;
#pragma unroll
        for (int t = 0; t < 8; t++) {
            float e0 = __expf(acc[t][0] - mn0), e1 = __expf(acc[t][1] - mn0);
            float e2 = __expf(acc[t][2] - mn1), e3 = __expf(acc[t][3] - mn1);
            const __half2 h01 = __floats2half2_rn(e0, e1);
            const __half2 h23 = __floats2half2_rn(e2, e3);
            const float2 q01 = __half22float2(h01), q23 = __half22float2(h23);
            ps0 += q01.x + q01.y; ps1 += q23.x + q23.y;
            const int cc = t * 8 + 2 * qid;
            *(__half2*)&estw[grp * 72 + cc]       = h01;
            *(__half2*)&estw[(grp + 8) * 72 + cc] = h23;
            *(__half2*)&eh[(size_t)lr0 * cNP + p0 + cc] = h01;
            *(__half2*)&eh[(size_t)lr1 * cNP + p0 + cc] = h23;
            accv[t][0] *= f0; accv[t][1] *= f0; accv[t][2] *= f1; accv[t][3] *= f1;
        }
        s0 = s0 * f0 + ps0; s1 = s1 * f1 + ps1;
        if (qid == 0) {
            g_mthen[((size_t)bh * 32 + pt) * cNL + l0 + lr0] = mn0;
            g_mthen[((size_t)bh * 32 + pt) * cNL + l0 + lr1] = mn1;
        }
        __syncwarp();                        // est visible within warp

        // av MMA (fp16): A = e (est), B = P2 tile
#pragma unroll
        for (int kk = 0; kk < 4; kk++) {
            uint32_t a[4];
            load_afr_h(estw, 0, grp, qid, kk, a);
#pragma unroll
            for (int t = 0; t < 8; t++) {
                uint32_t bf[2];
                load_bfr_h(P2h, t * 8 + grp, kk, qid, bf);
                mma_f16(accv[t], a, bf);
            }
        }
    }

    // finalize: quad-reduce sums, write sinv + l3h
    s0 += __shfl_xor_sync(0xffffffffu, s0, 1);
    s0 += __shfl_xor_sync(0xffffffffu, s0, 2);
    s1 += __shfl_xor_sync(0xffffffffu, s1, 1);
    s1 += __shfl_xor_sync(0xffffffffu, s1, 2);
    const float inv0 = 1.0f / s0, inv1 = 1.0f / s1;
    if (qid == 0) {
        g_sinv[bh * cNL + l0 + lr0] = inv0;
        g_sinv[bh * cNL + l0 + lr1] = inv1;
    }
    const size_t orow0 = ((size_t)(b * cNL) + l0 + lr0) * 512 + h * 64;
    const size_t orow1 = ((size_t)(b * cNL) + l0 + lr1) * 512 + h * 64;
#pragma unroll
    for (int t = 0; t < 8; t++) {
        const int cc = t * 8 + 2 * qid;
        *(float2*)&g_l3h[orow0 + cc] =
            make_float2(accv[t][0] * inv0, accv[t][1] * inv0);
        *(float2*)&g_l3h[orow1 + cc] =
            make_float2(accv[t][2] * inv1, accv[t][3] * inv1);
    }
}

// =====================================================================
// atv (tf32, transpose-free, R15 version) + register double-buffering.
// =====================================================================
__global__ __launch_bounds__(256) void atv_mma() {
    __shared__ float Ael[32 * 136];  // e tile [l][p=128], stride 136
    __shared__ float Al2[64 * 36];   // scaled L2t [d][l=32], stride 36
    __shared__ float cfa[2][256];
    __shared__ float svs[256];
#define ATS(p_, d_) Ael[(p_) * 68 + (d_)]   // epilogue stage overlays Ael
    const int bh = blockIdx.y, b = bh >> 3, h = bh & 7;
    const int p0 = blockIdx.x * 128;
    const int tid = threadIdx.x, wid = tid >> 5, lane = tid & 31, grp = lane >> 2, qid = lane & 3;
    const int mtw = wid & 3, nw = wid >> 2;   // 4 d-tiles x 2 p-halves
    const int m0 = mtw * 16, n0 = nw * 64;
    const __half* eb = g_att + (size_t)bh * cNL * cNP;
    const float* L2b = g_L2t + (size_t)bh * 64 * cNL;
    const float* sv = g_sinv + (size_t)bh * cNL;
    const int pt0 = p0 >> 6;

    for (int i = tid; i < 512; i += 256) {
        int v = i >> 8, j = i & 255;
        float mf = g_mthen[((size_t)bh * 32 + 31) * cNL + j];
        float mt = g_mthen[((size_t)bh * 32 + pt0 + v) * cNL + j];
        cfa[v][j] = __expf(mt - mf);
    }
    for (int i = tid; i < 256; i += 256) svs[i] = sv[i];

    // prefetch tile lt=0 into registers
    uint4 eReg[2];
    float4 l2Reg[2];
#pragma unroll
    for (int j = 0; j < 2; j++) {
        const int i = tid + j * 256;
        const int r = i >> 4, c8 = (i & 15) * 8;
        eReg[j] = *(const uint4*)&eb[(size_t)r * cNP + p0 + c8];
        const int d = i >> 3, k4 = (i & 7) * 4;
        l2Reg[j] = *(const float4*)&L2b[(size_t)d * cNL + k4];
    }

    float acc[8][4] = {};
    for (int lt = 0; lt < 8; lt++) {
        const int lb = lt * 32;
        __syncthreads();   // prev MMA done; cfa/svs ready on first iter
        // store prefetched regs (with cf / sv scaling)
#pragma unroll
        for (int j = 0; j < 2; j++) {
            const int i = tid + j * 256;
            {
                const int r = i >> 4, c8 = (i & 15) * 8;
                float2 f0 = __half22float2(*(__half2*)&eReg[j].x);
                float2 f1 = __half22float2(*(__half2*)&eReg[j].y);
                float2 f2 = __half22float2(*(__half2*)&eReg[j].z);
                float2 f3 = __half22float2(*(__half2*)&eReg[j].w);
                const float cf = cfa[c8 >> 6][lb + r];
                float4 o0 = make_float4(tf32f(f0.x * cf), tf32f(f0.y * cf),
                                        tf32f(f1.x * cf), tf32f(f1.y * cf));
                float4 o1 = make_float4(tf32f(f2.x * cf), tf32f(f2.y * cf),
                                        tf32f(f3.x * cf), tf32f(f3.y * cf));
                *(float4*)&Ael[r * 136 + c8]     = o0;
                *(float4*)&Ael[r * 136 + c8 + 4] = o1;
            }
            {
                const int d = i >> 3, k4 = (i & 7) * 4;
                float4 v = l2Reg[j];
                v.x = tf32f(v.x * svs[lb + k4]);
                v.y = tf32f(v.y * svs[lb + k4 + 1]);
                v.z = tf32f(v.z * svs[lb + k4 + 2]);
                v.w = tf32f(v.w * svs[lb + k4 + 3]);
                *(float4*)&Al2[d * 36 + k4] = v;
            }
        }
        // prefetch lt+1 (LDGs overlap the MMA below)
        if (lt < 7) {
            const int lb2 = lb + 32;
#pragma unroll
            for (int j = 0; j < 2; j++) {
                const int i = tid + j * 256;
                const int r = i >> 4, c8 = (i & 15) * 8;
                eReg[j] = *(const uint4*)&eb[(size_t)(lb2 + r) * cNP + p0 + c8];
                const int d = i >> 3, k4 = (i & 7) * 4;
                l2Reg[j] = *(const float4*)&L2b[(size_t)d * cNL + lb2 + k4];
            }
        }
        __syncthreads();
#pragma unroll
        for (int kk = 0; kk < 4; kk++) {
            const int k0 = kk * 8;
            uint32_t a[4] = { __float_as_uint(Al2[(m0 + grp) * 36 + k0 + qid]),
                              __float_as_uint(Al2[(m0 + grp + 8) * 36 + k0 + qid]),
                              __float_as_uint(Al2[(m0 + grp) * 36 + k0 + qid + 4]),
                              __float_as_uint(Al2[(m0 + grp + 8) * 36 + k0 + qid + 4]) };
#pragma unroll
            for (int t = 0; t < 8; t++) {
                const int n = n0 + t * 8 + grp;
                uint32_t bf[2] = { __float_as_uint(Ael[(k0 + qid) * 136 + n]),
                                   __float_as_uint(Ael[(k0 + qid + 4) * 136 + n]) };
                mma_tf32(acc[t], a, bf);
            }
        }
    }

#pragma unroll
    for (int half = 0; half < 2; half++) {
        __syncthreads();
        if (nw == half) {
            const int d0 = m0 + grp, d1 = d0 + 8;
#pragma unroll
            for (int t = 0; t < 8; t++) {
                const int pl = t * 8 + 2 * qid;
                ATS(pl, d0)     = tf32f(acc[t][0]);
                ATS(pl + 1, d0) = tf32f(acc[t][1]);
                ATS(pl, d1)     = tf32f(acc[t][2]);
                ATS(pl + 1, d1) = tf32f(acc[t][3]);
            }
        }
        __syncthreads();
        const int pg = p0 + half * 64;
        for (int i = tid; i < 1024; i += 256) {
            int pl = i >> 4, c4 = (i & 15) * 4;
            *(float4*)&g_p3h[((size_t)(b * cNP) + pg + pl) * 512 + h * 64 + c4] =
                *(float4*)&ATS(pl, c4);
        }
    }
#undef ATS
}

// =====================================================================
// fc_fused (merged lig+prot) with 2-stage cp.async PIPELINE for fc1 (K=32 tiles).
// =====================================================================
__global__ __launch_bounds__(256) void fc_fused(const float* __restrict__ lig,
                                                const float* __restrict__ prot,
                                                const float* __restrict__ b1l,
                                                const float* __restrict__ b2l,
                                                const float* __restrict__ b1p,
                                                const float* __restrict__ b2p,
                                                float* __restrict__ out) {
    __shared__ float SM[9216];
#define A1(buf_, r_, k_) SM[(buf_) * 2304 + (r_) * 36 + (k_)]
#define B1(buf_, n_, k_) SM[4608 + (buf_) * 2304 + (n_) * 36 + (k_)]
#define CSF(r_, c_) SM[(r_) * 68 + (c_)]
    float* B2s = SM + 4608;   // fc2 weight tile, stride 68
    const int which = (blockIdx.x >= 64) ? 1 : 0;
    const int bx = which ? (blockIdx.x - 64) : blockIdx.x;
    const float* X = which ? g_p3h : g_l3h;
    const float* W1 = g_f1T[which];
    const float* W2 = g_f2T[which];
    const float* orig = which ? prot : lig;
    const float* b1 = which ? b1p : b1l;
    const float* b2 = which ? b2p : b2l;
    const int N = which ? cNP : cNL;
    const int row_off = which ? cNL : 0;
    const int row0 = bx * 64;
    const int tid = threadIdx.x, wid = tid >> 5, lane = tid & 31, grp = lane >> 2, qid = lane & 3;
    const int mtw = wid & 3, nw = wid >> 2, m0 = mtw * 16, n0 = nw * 32;
    const int r0l = m0 + grp, r1l = r0l + 8;

#define FILL_KT(kt_, buf_)                                                        \
    do {                                                                          \
        const int kb_ = (kt_) * 32;                                               \
        for (int i = tid; i < 512; i += 256) {                                    \
            int r_ = i >> 3, k4_ = (i & 7) * 4;                                   \
            cpa16(&A1(buf_, r_, k4_), &X[(size_t)(row0 + r_) * 512 + kb_ + k4_]); \
        }                                                                         \
        for (int i = tid; i < 512; i += 256) {                                    \
            int n_ = i >> 3, k4_ = (i & 7) * 4;                                   \
            cpa16(&B1(buf_, n_, k4_), &W1[(size_t)n_ * 512 + kb_ + k4_]);         \
        }                                                                         \
        CP_COMMIT();                                                              \
    } while (0)

    FILL_KT(0, 0);
    FILL_KT(1, 1);

    float acc[4][4] = {};
    for (int kt = 0; kt < 16; kt++) {
        if (kt < 15) { CP_WAIT(1); } else { CP_WAIT(0); }
        __syncthreads();
        const int buf = kt & 1;
#pragma unroll
        for (int kk = 0; kk < 4; kk++) {
            const int k0 = kk * 8;
            uint32_t a[4] = { __float_as_uint(A1(buf, m0 + grp, k0 + qid)),
                              __float_as_uint(A1(buf, m0 + grp + 8, k0 + qid)),
                              __float_as_uint(A1(buf, m0 + grp, k0 + qid + 4)),
                              __float_as_uint(A1(buf, m0 + grp + 8, k0 + qid + 4)) };
#pragma unroll
            for (int t = 0; t < 4; t++) {
                const int n = n0 + t * 8 + grp;
                uint32_t bf[2] = { __float_as_uint(B1(buf, n, k0 + qid)),
                                   __float_as_uint(B1(buf, n, k0 + qid + 4)) };
                mma_tf32(acc[t], a, bf);
            }
        }
        __syncthreads();
        if (kt + 2 < 16) FILL_KT(kt + 2, kt & 1);
    }
#undef FILL_KT

#pragma unroll
    for (int t = 0; t < 4; t++) {
        const int c = n0 + t * 8 + 2 * qid;
        const float bv0 = b1[c], bv1 = b1[c + 1];
        CSF(r0l, c)     = tf32f(acc[t][0] + bv0);
        CSF(r0l, c + 1) = tf32f(acc[t][1] + bv1);
        CSF(r1l, c)     = tf32f(acc[t][2] + bv0);
        CSF(r1l, c + 1) = tf32f(acc[t][3] + bv1);
    }
    for (int i = tid; i < 1024; i += 256) {
        int n = i >> 4, k4 = (i & 15) * 4;
        cpa16(&B2s[n * 68 + k4], &W2[(size_t)n * 128 + k4]);
    }
    CP_COMMIT();
    CP_WAIT(0);
    __syncthreads();

    float acc2[4][4] = {};
#pragma unroll
    for (int kk = 0; kk < 8; kk++) {
        uint32_t a[4];
        load_afr(SM, m0, grp, qid, kk, a);
#pragma unroll
        for (int t = 0; t < 4; t++) {
            uint32_t bf[2];
            load_bfr(B2s, n0 + t * 8 + grp, kk, qid, bf);
            mma_tf32(acc2[t], a, bf);
        }
    }
    __syncthreads();
    for (int i = tid; i < 1024; i += 256) {
        int r = i >> 4, c4 = (i & 15) * 4;
        float4 v = *(const float4*)&orig[(size_t)(row0 + r) * 64 + c4];
        v.x = tf32f(v.x); v.y = tf32f(v.y); v.z = tf32f(v.z); v.w = tf32f(v.w);
        *(float4*)&CSF(r, c4) = v;
    }
    for (int i = tid; i < 1024; i += 256) {
        int n = i >> 4, k4 = (i & 15) * 4;
        cpa16(&B2s[n * 68 + k4], &W2[(size_t)n * 128 + 64 + k4]);
    }
    CP_COMMIT();
    CP_WAIT(0);
    __syncthreads();
#pragma unroll
    for (int kk = 0; kk < 8; kk++) {
        uint32_t a[4];
        load_afr(SM, m0, grp, qid, kk, a);
#pragma unroll
        for (int t = 0; t < 4; t++) {
            uint32_t bf[2];
            load_bfr(B2s, n0 + t * 8 + grp, kk, qid, bf);
            mma_tf32(acc2[t], a, bf);
        }
    }
    __syncthreads();
#pragma unroll
    for (int t = 0; t < 4; t++) {
        const int c = n0 + t * 8 + 2 * qid;
        const float bv0 = b2[c], bv1 = b2[c + 1];
        CSF(r0l, c)     = fmaxf(acc2[t][0] + bv0, 0.f);
        CSF(r0l, c + 1) = fmaxf(acc2[t][1] + bv1, 0.f);
        CSF(r1l, c)     = fmaxf(acc2[t][2] + bv0, 0.f);
        CSF(r1l, c + 1) = fmaxf(acc2[t][3] + bv1, 0.f);
    }
    __syncthreads();
    const int b = row0 / N, nbase = row0 % N;
    for (int i = tid; i < 1024; i += 256) {
        int r = i >> 4, c4 = (i & 15) * 4;
        *(float4*)&out[((size_t)b * cNT + row_off + nbase + r) * 64 + c4] =
            *(float4*)&CSF(r, c4);
    }
#undef A1
#undef B1
#undef CSF
}

// =====================================================================
extern "C" void kernel_launch(void* const* d_in, const int* in_sizes, int n_in,
                              void* d_out, int out_size) {
    (void)in_sizes; (void)n_in; (void)out_size;
    const float* ligand = (const float*)d_in[0];
    const float* prot   = (const float*)d_in[1];
    const float* dist   = (const float*)d_in[2];
    const float* b_l1 = (const float*)d_in[4];
    const float* b_l2 = (const float*)d_in[6];
    const float* b_p1 = (const float*)d_in[8];
    const float* b_p2 = (const float*)d_in[10];
    const float* fc11_b = (const float*)d_in[12];
    const float* fc12_b = (const float*)d_in[14];
    const float* fc21_b = (const float*)d_in[16];
    const float* fc22_b = (const float*)d_in[18];
    float* out = (float*)d_out;

    prep_weights<<<832, 256>>>((const float*)d_in[3], (const float*)d_in[5],
                               (const float*)d_in[7], (const float*)d_in[9],
                               (const float*)d_in[11], (const float*)d_in[15],
                               (const float*)d_in[13], (const float*)d_in[17]);
    proj2<<<576, 256>>>(ligand, prot, b_l1, b_l2, b_p1, b_p2);
    energy_av<<<dim3(cNL / 64, cB * cH), 128>>>(dist);
    atv_mma<<<dim3(cNP / 128, cB * cH), 256>>>();
    fc_fused<<<576, 256>>>(ligand, prot, fc11_b, fc12_b, fc21_b, fc22_b, out);
}